// round 13
// baseline (speedup 1.0000x reference)
#include <cuda_runtime.h>
#include <cuda_bf16.h>
#include <math.h>

// DynamicRouter: logits = x @ W^T + b + 0.1*noise ; top-2 ; sparse softmax.
// x[B=8,S=4096,D=768] f32, W[E=8,D=768] f32, b[8] f32, noise[B,S,8] f32.
//
// R13: PERSISTENT kernel + atomic work stealing over 32-token passes.
// 444 CTAs (3/SM) stage W once, then loop: pop ticket -> R7 cp.async
// 3-stage ring pipeline -> epilogue. Kills wave quantization, repeated
// W staging, and per-CTA pipeline fill/drain that capped HBM at ~4TB/s.

#define D_DIM        768
#define E_DIM        8
#define TOK_PER_WARP 4
#define WARPS        8
#define BLOCK        (WARPS * 32)
#define TOK_PER_BLK  (WARPS * TOK_PER_WARP)   // 32
#define D4           (D_DIM / 4)              // 192
#define NCHUNK       (D4 / 32)                // 6
#define NSTAGE       3
#define SW_F4        (E_DIM * D4)             // 1536 float4 = 24 KB
#define SX_WARP_F4   (NSTAGE * TOK_PER_WARP * 32)   // 384 float4 = 6 KB/warp
#define SMEM_BYTES   ((SW_F4 + WARPS * SX_WARP_F4) * 16)  // 73728
#define GRID_CTAS    444                      // 148 SMs x 3 CTAs
#define NOISE_STD    0.1f

#define CP_ASYNC16(dst32, src) \
    asm volatile("cp.async.cg.shared.global [%0], [%1], 16;" \
                 :: "r"(dst32), "l"(src) : "memory")
#define CP_COMMIT() asm volatile("cp.async.commit_group;" ::: "memory")
#define CP_WAIT(n)  asm volatile("cp.async.wait_group %0;" :: "n"(n) : "memory")

__device__ unsigned g_ticket;   // reset to 0 by cudaMemsetAsync before launch

__global__ __launch_bounds__(BLOCK, 3)
void router_kernel(const float* __restrict__ x,
                   const float* __restrict__ W,
                   const float* __restrict__ b,
                   const float* __restrict__ noise,
                   float* __restrict__ out,
                   int nTokens, int nPasses, int writeIdx)
{
    extern __shared__ float4 smem[];
    float4* sW4 = smem;                 // [E_DIM*D4], 16B lane stride: conflict-free
    float4* sX  = smem + SW_F4;         // ring [WARPS][NSTAGE][TOK*32]
    __shared__ unsigned sTicket;

    const int tid  = threadIdx.x;
    const int lane = tid & 31;
    const int wid  = tid >> 5;

    // Stage W into shared ONCE per persistent CTA
    {
        const float4* Wg = reinterpret_cast<const float4*>(W);
        #pragma unroll
        for (int i = 0; i < SW_F4 / BLOCK; i++)
            sW4[i * BLOCK + tid] = Wg[i * BLOCK + tid];
    }

    const float4* xb = reinterpret_cast<const float4*>(x);
    float4* myX = sX + wid * SX_WARP_F4;
    const unsigned myX32 = (unsigned)__cvta_generic_to_shared(myX);

    for (;;) {
        // pop next 32-token pass (work stealing); barrier also covers W stage
        if (tid == 0) sTicket = atomicAdd(&g_ticket, 1u);
        __syncthreads();
        const unsigned pass = sTicket;
        if (pass >= (unsigned)nPasses) break;

        const int tokBase = (int)pass * TOK_PER_BLK + wid * TOK_PER_WARP;

        // clamped per-token row pointers (robust to a partial final pass)
        const float4* xt[TOK_PER_WARP];
        #pragma unroll
        for (int t = 0; t < TOK_PER_WARP; t++) {
            int tk = tokBase + t;
            if (tk > nTokens - 1) tk = nTokens - 1;
            xt[t] = xb + (size_t)tk * D4;
        }

        float acc[TOK_PER_WARP * E_DIM];
        #pragma unroll
        for (int v = 0; v < TOK_PER_WARP * E_DIM; v++) acc[v] = 0.0f;

        auto issue = [&](int c, int s) {
            #pragma unroll
            for (int t = 0; t < TOK_PER_WARP; t++)
                CP_ASYNC16(myX32 + (unsigned)(((s * TOK_PER_WARP + t) * 32 + lane) * 16),
                           xt[t] + c * 32 + lane);
            CP_COMMIT();
        };

        auto compute = [&](int c, int s) {
            float4 xv[TOK_PER_WARP];
            #pragma unroll
            for (int t = 0; t < TOK_PER_WARP; t++)
                xv[t] = myX[(s * TOK_PER_WARP + t) * 32 + lane];
            const int p = c * 32 + lane;
            #pragma unroll
            for (int e = 0; e < E_DIM; e++) {
                const float4 wv = sW4[e * D4 + p];   // LDS.128, reused x4 tokens
                #pragma unroll
                for (int t = 0; t < TOK_PER_WARP; t++)
                    acc[t * E_DIM + e] += xv[t].x * wv.x + xv[t].y * wv.y
                                        + xv[t].z * wv.z + xv[t].w * wv.w;
            }
        };

        // fully unrolled 3-deep pipeline over 6 chunks
        issue(0, 0); issue(1, 1); issue(2, 2);
        CP_WAIT(2); compute(0, 0); issue(3, 0);
        CP_WAIT(2); compute(1, 1); issue(4, 1);
        CP_WAIT(2); compute(2, 2); issue(5, 2);
        CP_WAIT(2); compute(3, 0);
        CP_WAIT(1); compute(4, 1);
        CP_WAIT(0); compute(5, 2);

        // Log-halving butterfly: lane l ends with the full 32-lane sum for
        // value index v == l (v = t*8 + e). Slot-preserving, so clamped
        // (duplicate) tokens only affect their own masked slots.
        #pragma unroll
        for (int m = 16; m >= 1; m >>= 1) {
            const bool upper = (lane & m) != 0;
            #pragma unroll
            for (int i = 0; i < m; i++) {
                const float lo = acc[i], hi = acc[i + m];
                const float send = upper ? lo : hi;
                const float recv = __shfl_xor_sync(0xFFFFFFFFu, send, m);
                acc[i] = upper ? (hi + recv) : (lo + recv);
            }
        }
        const float sum = acc[0];

        const int t = lane >> 3;
        const int e = lane & 7;
        const long tok = (long)tokBase + t;
        const bool valid = tok < nTokens;

        const float nval = valid ? __ldg(noise + (size_t)tokBase * E_DIM + lane) : 0.0f;
        const float logit = sum + __ldg(b + e) + NOISE_STD * nval;

        // top-1 over each 8-lane expert group (ties -> lower index)
        float v1 = logit; int i1 = e;
        #pragma unroll
        for (int off = 1; off < 8; off <<= 1) {
            const float ov = __shfl_xor_sync(0xFFFFFFFFu, v1, off);
            const int   oi = __shfl_xor_sync(0xFFFFFFFFu, i1, off);
            if (ov > v1 || (ov == v1 && oi < i1)) { v1 = ov; i1 = oi; }
        }
        // top-2: exclude winner, reduce again
        float v2 = (e == i1) ? -INFINITY : logit; int i2 = e;
        #pragma unroll
        for (int off = 1; off < 8; off <<= 1) {
            const float ov = __shfl_xor_sync(0xFFFFFFFFu, v2, off);
            const int   oi = __shfl_xor_sync(0xFFFFFFFFu, i2, off);
            if (ov > v2 || (ov == v2 && oi < i2)) { v2 = ov; i2 = oi; }
        }

        // 2-element softmax (arg <= 0, no overflow)
        const float ed  = __expf(v2 - v1);
        const float inv = 1.0f / (1.0f + ed);
        const float p   = (e == i1) ? inv : ((e == i2) ? ed * inv : 0.0f);

        if (valid) {
            out[(size_t)tokBase * E_DIM + lane] = p;   // coalesced 128B/warp
            if (writeIdx && e == 0) {
                float* idxOut = out + (size_t)nTokens * E_DIM;
                idxOut[tok * 2 + 0] = (float)i1;
                idxOut[tok * 2 + 1] = (float)i2;
            }
        }
        __syncthreads();   // protect sTicket before next pop
    }
}

extern "C" void kernel_launch(void* const* d_in, const int* in_sizes, int n_in,
                              void* d_out, int out_size)
{
    const float* x     = (const float*)d_in[0];
    const float* W     = (const float*)d_in[1];
    const float* b     = (const float*)d_in[2];
    const float* noise = (const float*)d_in[3];
    float* out = (float*)d_out;

    const int nTokens = in_sizes[3] / E_DIM;          // B*S from noise elem count
    const int nPasses = (nTokens + TOK_PER_BLK - 1) / TOK_PER_BLK;
    const int writeIdx = (out_size >= nTokens * E_DIM + nTokens * 2) ? 1 : 0;

    // >48KB dynamic smem opt-in (idempotent; capture-safe)
    cudaFuncSetAttribute(router_kernel,
                         cudaFuncAttributeMaxDynamicSharedMemorySize,
                         SMEM_BYTES);

    // reset the work-stealing ticket (async memset is graph-capturable)
    void* ticketAddr = nullptr;
    cudaGetSymbolAddress(&ticketAddr, g_ticket);
    cudaMemsetAsync(ticketAddr, 0, sizeof(unsigned));

    router_kernel<<<GRID_CTAS, BLOCK, SMEM_BYTES>>>(x, W, b, noise, out,
                                                    nTokens, nPasses, writeIdx);
}

// round 14
// speedup vs baseline: 1.1547x; 1.1547x over previous
#include <cuda_runtime.h>
#include <cuda_bf16.h>
#include <math.h>

// DynamicRouter: logits = x @ W^T + b + 0.1*noise ; top-2 ; sparse softmax.
// x[B=8,S=4096,D=768] f32, W[E=8,D=768] f32, b[8] f32, noise[B,S,8] f32.
//
// R14: occupancy done right. TOK=3 (acc 24 regs) + 2-stage cp.async ring
// (register-cheap staging) + __launch_bounds__(256,4) -> target <=64 regs
// WITHOUT spills, 48KB smem -> 4 CTAs/SM = 32 warps (+33% latency tolerance
// vs the 24-warp plateau that held 7 variants at ~25us).

#define D_DIM        768
#define E_DIM        8
#define TOK_PER_WARP 3
#define WARPS        8
#define BLOCK        (WARPS * 32)
#define TOK_PER_BLK  (WARPS * TOK_PER_WARP)   // 24
#define D4           (D_DIM / 4)              // 192
#define NCHUNK       (D4 / 32)                // 6
#define NSTAGE       2
#define SW_F4        (E_DIM * D4)             // 1536 float4 = 24 KB
#define SX_WARP_F4   (NSTAGE * TOK_PER_WARP * 32)   // 192 float4 = 3 KB/warp
#define SMEM_BYTES   ((SW_F4 + WARPS * SX_WARP_F4) * 16)  // 49152
#define NOISE_STD    0.1f

#define CP_ASYNC16(dst32, src) \
    asm volatile("cp.async.cg.shared.global [%0], [%1], 16;" \
                 :: "r"(dst32), "l"(src) : "memory")
#define CP_COMMIT() asm volatile("cp.async.commit_group;" ::: "memory")
#define CP_WAIT(n)  asm volatile("cp.async.wait_group %0;" :: "n"(n) : "memory")

__global__ __launch_bounds__(BLOCK, 4)
void router_kernel(const float* __restrict__ x,
                   const float* __restrict__ W,
                   const float* __restrict__ b,
                   const float* __restrict__ noise,
                   float* __restrict__ out,
                   int nTokens, int writeIdx)
{
    extern __shared__ float4 smem[];
    float4* sW4 = smem;                 // [E_DIM*D4], 16B lane stride: conflict-free
    float4* sX  = smem + SW_F4;         // ring [WARPS][NSTAGE][TOK*32]

    const int tid  = threadIdx.x;
    const int lane = tid & 31;
    const int wid  = tid >> 5;

    // Stage W into shared once (coalesced float4 copy of contiguous 24 KB)
    {
        const float4* Wg = reinterpret_cast<const float4*>(W);
        #pragma unroll
        for (int i = 0; i < SW_F4 / BLOCK; i++)
            sW4[i * BLOCK + tid] = Wg[i * BLOCK + tid];
    }
    __syncthreads();

    const int tokBase = blockIdx.x * TOK_PER_BLK + wid * TOK_PER_WARP;
    if (tokBase >= nTokens) return;

    // Single clamped base pointer; per-token offsets are compile-time imms.
    int tkClamp = tokBase;
    if (tkClamp > nTokens - TOK_PER_WARP) tkClamp = nTokens - TOK_PER_WARP;
    const float4* x4 = reinterpret_cast<const float4*>(x) + (size_t)tkClamp * D4;
    // NOTE: when clamped, warp computes the last 3 valid tokens; stores are
    // masked against the true token id below, so duplicates are discarded.

    float4* myX = sX + wid * SX_WARP_F4;
    const unsigned myX32 = (unsigned)__cvta_generic_to_shared(myX);

    float acc[TOK_PER_WARP * E_DIM];    // 24 regs
    #pragma unroll
    for (int v = 0; v < TOK_PER_WARP * E_DIM; v++) acc[v] = 0.0f;

    auto issue = [&](int c, int s) {
        #pragma unroll
        for (int t = 0; t < TOK_PER_WARP; t++)
            CP_ASYNC16(myX32 + (unsigned)(((s * TOK_PER_WARP + t) * 32 + lane) * 16),
                       x4 + (size_t)t * D4 + c * 32 + lane);
        CP_COMMIT();
    };

    auto compute = [&](int c, int s) {
        float4 xv[TOK_PER_WARP];
        #pragma unroll
        for (int t = 0; t < TOK_PER_WARP; t++)
            xv[t] = myX[(s * TOK_PER_WARP + t) * 32 + lane];
        const int p = c * 32 + lane;
        #pragma unroll
        for (int e = 0; e < E_DIM; e++) {
            const float4 wv = sW4[e * D4 + p];   // LDS.128, reused x3 tokens
            #pragma unroll
            for (int t = 0; t < TOK_PER_WARP; t++)
                acc[t * E_DIM + e] += xv[t].x * wv.x + xv[t].y * wv.y
                                    + xv[t].z * wv.z + xv[t].w * wv.w;
        }
    };

    // 2-stage pipeline over 6 chunks
    issue(0, 0); issue(1, 1);
    CP_WAIT(1); compute(0, 0); issue(2, 0);
    CP_WAIT(1); compute(1, 1); issue(3, 1);
    CP_WAIT(1); compute(2, 0); issue(4, 0);
    CP_WAIT(1); compute(3, 1); issue(5, 1);
    CP_WAIT(1); compute(4, 0);
    CP_WAIT(0); compute(5, 1);

    // Zero-pad to 32 slots, then log-halving butterfly: lane l ends with the
    // full 32-lane sum of slot l (slot v = t*8 + e for v < 24).
    float red[32];
    #pragma unroll
    for (int v = 0; v < TOK_PER_WARP * E_DIM; v++) red[v] = acc[v];
    #pragma unroll
    for (int v = TOK_PER_WARP * E_DIM; v < 32; v++) red[v] = 0.0f;

    #pragma unroll
    for (int m = 16; m >= 1; m >>= 1) {
        const bool upper = (lane & m) != 0;
        #pragma unroll
        for (int i = 0; i < m; i++) {
            const float lo = red[i], hi = red[i + m];
            const float send = upper ? lo : hi;
            const float recv = __shfl_xor_sync(0xFFFFFFFFu, send, m);
            red[i] = upper ? (hi + recv) : (lo + recv);
        }
    }
    const float sum = red[0];

    const int t = lane >> 3;            // slot token (0..3; only 0..2 valid)
    const int e = lane & 7;             // expert
    const long tok = (long)tkClamp + t;
    const bool valid = (lane < TOK_PER_WARP * E_DIM) && (tok < nTokens)
                     && (tok >= tokBase);   // discard clamp duplicates

    const float nval = valid ? __ldg(noise + (size_t)tkClamp * E_DIM + lane) : 0.0f;
    const float logit = sum + __ldg(b + e) + NOISE_STD * nval;

    // top-1 over each 8-lane expert group (ties -> lower index, jax top_k)
    float v1 = logit; int i1 = e;
    #pragma unroll
    for (int off = 1; off < 8; off <<= 1) {
        const float ov = __shfl_xor_sync(0xFFFFFFFFu, v1, off);
        const int   oi = __shfl_xor_sync(0xFFFFFFFFu, i1, off);
        if (ov > v1 || (ov == v1 && oi < i1)) { v1 = ov; i1 = oi; }
    }
    // top-2: exclude winner, reduce again
    float v2 = (e == i1) ? -INFINITY : logit; int i2 = e;
    #pragma unroll
    for (int off = 1; off < 8; off <<= 1) {
        const float ov = __shfl_xor_sync(0xFFFFFFFFu, v2, off);
        const int   oi = __shfl_xor_sync(0xFFFFFFFFu, i2, off);
        if (ov > v2 || (ov == v2 && oi < i2)) { v2 = ov; i2 = oi; }
    }

    // 2-element softmax (arg <= 0, no overflow)
    const float ed  = __expf(v2 - v1);
    const float inv = 1.0f / (1.0f + ed);
    const float p   = (e == i1) ? inv : ((e == i2) ? ed * inv : 0.0f);

    if (valid) {
        out[(size_t)tkClamp * E_DIM + lane] = p;   // 96B contiguous per warp
        if (writeIdx && e == 0) {
            float* idxOut = out + (size_t)nTokens * E_DIM;
            idxOut[tok * 2 + 0] = (float)i1;
            idxOut[tok * 2 + 1] = (float)i2;
        }
    }
}

extern "C" void kernel_launch(void* const* d_in, const int* in_sizes, int n_in,
                              void* d_out, int out_size)
{
    const float* x     = (const float*)d_in[0];
    const float* W     = (const float*)d_in[1];
    const float* b     = (const float*)d_in[2];
    const float* noise = (const float*)d_in[3];
    float* out = (float*)d_out;

    const int nTokens = in_sizes[3] / E_DIM;          // B*S from noise elem count
    const int writeIdx = (out_size >= nTokens * E_DIM + nTokens * 2) ? 1 : 0;

    // 48KB dynamic smem: opt-in is idempotent and capture-safe
    cudaFuncSetAttribute(router_kernel,
                         cudaFuncAttributeMaxDynamicSharedMemorySize,
                         SMEM_BYTES);

    const int grid = (nTokens + TOK_PER_BLK - 1) / TOK_PER_BLK;
    router_kernel<<<grid, BLOCK, SMEM_BYTES>>>(x, W, b, noise, out, nTokens, writeIdx);
}